// round 5
// baseline (speedup 1.0000x reference)
#include <cuda_runtime.h>

// EntropyLoss: heatmap [8, 20, 512, 512] f32 -> entropy [8] f32
//
// Per (n,c):  s = sum_{x>0} exp(x),  U = sum_{x>0} x*exp(x),  cnt = #positives
//             ent_c = (log s - U/s) / ln2          (max-shift cancels exactly)
// Per n:      out[n] = sum_c ent_c / sum_{c,hw} cnt
//
// R5: trade occupancy for MLP. launch_bounds(256,6) -> 40 regs, letting
// ptxas front-batch all 4 unrolled LDG.128 per warp (MLP_p1~4).
// SPLIT=5 -> 800 blocks = single wave at 6 blocks/SM (cap 888).
// Fused last-block finalize; counter self-resets for graph replay.

#define N_BATCH   8
#define N_CH      20
#define CHANNELS  (N_BATCH * N_CH)   // 160
#define HW        (512 * 512)        // 262144 elems/channel
#define HW4       (HW / 4)           // 65536 float4/channel
#define SPLIT     5                  // segments per channel
#define NBLK      (CHANNELS * SPLIT) // 800 blocks (single wave @ 6/SM)
#define TPB       256

__device__ float g_ps[NBLK];        // partial sum exp(x)
__device__ float g_pU[NBLK];        // partial sum x*exp(x)
__device__ float g_pc[NBLK];        // partial positive count
__device__ unsigned int g_done = 0; // arrival counter (reset by last block)

__global__ void __launch_bounds__(TPB, 6)
entropy_fused(const float* __restrict__ in, float* __restrict__ out)
{
    const int b   = blockIdx.x;
    const int ch  = b / SPLIT;        // 0..159
    const int seg = b % SPLIT;
    const int i0  = (int)(((long long)HW4 * seg) / SPLIT);
    const int i1  = (int)(((long long)HW4 * (seg + 1)) / SPLIT);
    const float4* __restrict__ p4 =
        reinterpret_cast<const float4*>(in + (size_t)ch * HW);

    float s = 0.f, U = 0.f, cnt = 0.f;

    #pragma unroll 4
    for (int i = i0 + threadIdx.x; i < i1; i += TPB) {
        float4 v = p4[i];
        if (v.x > 0.f) { float e = __expf(v.x); s += e; U += v.x * e; cnt += 1.f; }
        if (v.y > 0.f) { float e = __expf(v.y); s += e; U += v.y * e; cnt += 1.f; }
        if (v.z > 0.f) { float e = __expf(v.z); s += e; U += v.z * e; cnt += 1.f; }
        if (v.w > 0.f) { float e = __expf(v.w); s += e; U += v.w * e; cnt += 1.f; }
    }

    // warp reduce
    #pragma unroll
    for (int o = 16; o > 0; o >>= 1) {
        s   += __shfl_down_sync(0xffffffffu, s,   o);
        U   += __shfl_down_sync(0xffffffffu, U,   o);
        cnt += __shfl_down_sync(0xffffffffu, cnt, o);
    }

    __shared__ float sh_s[TPB / 32], sh_U[TPB / 32], sh_c[TPB / 32];
    const int w = threadIdx.x >> 5;
    const int l = threadIdx.x & 31;
    if (l == 0) { sh_s[w] = s; sh_U[w] = U; sh_c[w] = cnt; }
    __syncthreads();

    __shared__ bool is_last;
    if (threadIdx.x == 0) {
        float ts = 0.f, tU = 0.f, tc = 0.f;
        #pragma unroll
        for (int i = 0; i < TPB / 32; i++) { ts += sh_s[i]; tU += sh_U[i]; tc += sh_c[i]; }
        g_ps[b] = ts; g_pU[b] = tU; g_pc[b] = tc;
        __threadfence();                       // publish partials before arrival
        unsigned int old = atomicAdd(&g_done, 1u);
        is_last = (old == NBLK - 1);
    }
    __syncthreads();
    if (!is_last) return;

    // ---- finalize: only the last-arriving block runs this ----
    __threadfence();                           // acquire: see all partials

    __shared__ float ent_c[CHANNELS];
    __shared__ float cnt_c[CHANNELS];

    const int t = threadIdx.x;
    if (t == 0) g_done = 0;                    // reset for next graph replay
    if (t < CHANNELS) {
        float ss = 0.f, UU = 0.f, cc = 0.f;
        #pragma unroll
        for (int k = 0; k < SPLIT; k++) {
            ss += g_ps[t * SPLIT + k];
            UU += g_pU[t * SPLIT + k];
            cc += g_pc[t * SPLIT + k];
        }
        float ent = 0.f;
        if (ss > 0.f) {
            const float INV_LN2 = 1.4426950408889634f;
            ent = (logf(ss) - UU / ss) * INV_LN2;
        }
        ent_c[t] = ent;
        cnt_c[t] = cc;
    }
    __syncthreads();

    if (t < N_BATCH) {
        float es = 0.f, cs = 0.f;
        #pragma unroll
        for (int c = 0; c < N_CH; c++) {
            es += ent_c[t * N_CH + c];
            cs += cnt_c[t * N_CH + c];
        }
        out[t] = es / cs;
    }
}

extern "C" void kernel_launch(void* const* d_in, const int* in_sizes, int n_in,
                              void* d_out, int out_size)
{
    const float* heatmap = (const float*)d_in[0];
    float* out = (float*)d_out;
    entropy_fused<<<NBLK, TPB>>>(heatmap, out);
}

// round 6
// speedup vs baseline: 1.0697x; 1.0697x over previous
#include <cuda_runtime.h>

// EntropyLoss: heatmap [8, 20, 512, 512] f32 -> entropy [8] f32
//
// Per (n,c):  s = sum_{x>0} exp(x),  U = sum_{x>0} x*exp(x),  cnt = #positives
//             ent_c = (log s - U/s) / ln2          (max-shift cancels exactly)
// Per n:      out[n] = sum_c ent_c / sum_{c,hw} cnt
//
// R6: force MLP=4 — four named float4 loads issued back-to-back before any
// use (regs=31 in R4/R5 proved ptxas was running MLP~1, exposing DRAM
// latency). TPB=128, 12 blocks/SM (42-reg budget), SPLIT=11 -> 1760 blocks
// vs 1776 capacity: one wave, <1% imbalance. __ldcs: streamed, touched once.

#define N_BATCH   8
#define N_CH      20
#define CHANNELS  (N_BATCH * N_CH)   // 160
#define HW        (512 * 512)        // 262144 elems/channel
#define HW4       (HW / 4)           // 65536 float4/channel
#define SPLIT     11                 // segments per channel
#define NBLK      (CHANNELS * SPLIT) // 1760 blocks (cap 148*12=1776)
#define TPB       128

__device__ float g_ps[NBLK];        // partial sum exp(x)
__device__ float g_pU[NBLK];        // partial sum x*exp(x)
__device__ float g_pc[NBLK];        // partial positive count
__device__ unsigned int g_done = 0; // arrival counter (reset by last block)

// Branchless per-float4 accumulate (SEL, no branches)
#define ACC4(v)                                                   \
    do {                                                          \
        float e0 = __expf((v).x); float e1 = __expf((v).y);       \
        float e2 = __expf((v).z); float e3 = __expf((v).w);       \
        e0 = ((v).x > 0.f) ? e0 : 0.f;                            \
        e1 = ((v).y > 0.f) ? e1 : 0.f;                            \
        e2 = ((v).z > 0.f) ? e2 : 0.f;                            \
        e3 = ((v).w > 0.f) ? e3 : 0.f;                            \
        s += e0; U = fmaf((v).x, e0, U);                          \
        s += e1; U = fmaf((v).y, e1, U);                          \
        s += e2; U = fmaf((v).z, e2, U);                          \
        s += e3; U = fmaf((v).w, e3, U);                          \
        cnt += ((v).x > 0.f) ? 1.f : 0.f;                         \
        cnt += ((v).y > 0.f) ? 1.f : 0.f;                         \
        cnt += ((v).z > 0.f) ? 1.f : 0.f;                         \
        cnt += ((v).w > 0.f) ? 1.f : 0.f;                         \
    } while (0)

__global__ void __launch_bounds__(TPB, 12)
entropy_fused(const float* __restrict__ in, float* __restrict__ out)
{
    const int b   = blockIdx.x;
    const int ch  = b / SPLIT;        // 0..159
    const int seg = b % SPLIT;
    const int i0  = (int)(((long long)HW4 * seg) / SPLIT);
    const int i1  = (int)(((long long)HW4 * (seg + 1)) / SPLIT);
    const float4* __restrict__ p4 =
        reinterpret_cast<const float4*>(in + (size_t)ch * HW);

    float s = 0.f, U = 0.f, cnt = 0.f;

    int i = i0 + threadIdx.x;
    // main loop: 4 independent LDG.128 in flight per warp
    #pragma unroll 1
    for (; i + 3 * TPB < i1; i += 4 * TPB) {
        float4 a = __ldcs(p4 + i);
        float4 bb = __ldcs(p4 + i + TPB);
        float4 c = __ldcs(p4 + i + 2 * TPB);
        float4 d = __ldcs(p4 + i + 3 * TPB);
        ACC4(a); ACC4(bb); ACC4(c); ACC4(d);
    }
    // tail
    for (; i < i1; i += TPB) {
        float4 a = __ldcs(p4 + i);
        ACC4(a);
    }

    // warp reduce
    #pragma unroll
    for (int o = 16; o > 0; o >>= 1) {
        s   += __shfl_down_sync(0xffffffffu, s,   o);
        U   += __shfl_down_sync(0xffffffffu, U,   o);
        cnt += __shfl_down_sync(0xffffffffu, cnt, o);
    }

    __shared__ float sh_s[TPB / 32], sh_U[TPB / 32], sh_c[TPB / 32];
    const int w = threadIdx.x >> 5;
    const int l = threadIdx.x & 31;
    if (l == 0) { sh_s[w] = s; sh_U[w] = U; sh_c[w] = cnt; }
    __syncthreads();

    __shared__ bool is_last;
    if (threadIdx.x == 0) {
        float ts = 0.f, tU = 0.f, tc = 0.f;
        #pragma unroll
        for (int k = 0; k < TPB / 32; k++) { ts += sh_s[k]; tU += sh_U[k]; tc += sh_c[k]; }
        g_ps[b] = ts; g_pU[b] = tU; g_pc[b] = tc;
        __threadfence();                       // publish partials before arrival
        unsigned int old = atomicAdd(&g_done, 1u);
        is_last = (old == NBLK - 1);
    }
    __syncthreads();
    if (!is_last) return;

    // ---- finalize: only the last-arriving block runs this ----
    __threadfence();                           // acquire: see all partials

    __shared__ float ent_c[CHANNELS];
    __shared__ float cnt_c[CHANNELS];

    const int t = threadIdx.x;
    if (t == 0) g_done = 0;                    // reset for next graph replay
    // 128 threads, 160 channels: two passes
    for (int c = t; c < CHANNELS; c += TPB) {
        float ss = 0.f, UU = 0.f, cc = 0.f;
        #pragma unroll
        for (int k = 0; k < SPLIT; k++) {
            ss += g_ps[c * SPLIT + k];
            UU += g_pU[c * SPLIT + k];
            cc += g_pc[c * SPLIT + k];
        }
        float ent = 0.f;
        if (ss > 0.f) {
            const float INV_LN2 = 1.4426950408889634f;
            ent = (logf(ss) - UU / ss) * INV_LN2;
        }
        ent_c[c] = ent;
        cnt_c[c] = cc;
    }
    __syncthreads();

    if (t < N_BATCH) {
        float es = 0.f, cs = 0.f;
        #pragma unroll
        for (int c = 0; c < N_CH; c++) {
            es += ent_c[t * N_CH + c];
            cs += cnt_c[t * N_CH + c];
        }
        out[t] = es / cs;
    }
}

extern "C" void kernel_launch(void* const* d_in, const int* in_sizes, int n_in,
                              void* d_out, int out_size)
{
    const float* heatmap = (const float*)d_in[0];
    float* out = (float*)d_out;
    entropy_fused<<<NBLK, TPB>>>(heatmap, out);
}

// round 9
// speedup vs baseline: 1.0779x; 1.0077x over previous
#include <cuda_runtime.h>

// EntropyLoss: heatmap [8, 20, 512, 512] f32 -> entropy [8] f32
//
// Per (n,c):  s = sum_{x>0} exp(x),  U = sum_{x>0} x*exp(x),  cnt = #positives
//             ent_c = (log s - U/s) / ln2          (max-shift cancels exactly)
// Per n:      out[n] = sum_c ent_c / sum_{c,hw} cnt
//
// R7: software-pipelined mainloop (prefetch next 4 float4 while processing
// current 4) — R4-R6 all plateaued at DRAM=67% because loads were consumed
// in their own iteration (warp stalls right after issuing). Geometry for
// GB300's 152 SMs: TPB=128 x 10 blocks/SM = grid 1520, one exact wave;
// SPLIT=19 -> 3040 equal segments, 2 per block. Int counter, split
// accumulators. Fused last-block finalize, counter self-resets.

#define N_BATCH   8
#define N_CH      20
#define CHANNELS  (N_BATCH * N_CH)    // 160
#define HW        (512 * 512)         // 262144 elems/channel
#define HW4       (HW / 4)            // 65536 float4/channel
#define SPLIT     19                  // segments per channel
#define NSEG      (CHANNELS * SPLIT)  // 3040 segments
#define NBLK      1520                // 152 SMs x 10 blocks, single wave
#define SEG_PER_BLK (NSEG / NBLK)     // 2
#define TPB       128

__device__ float g_ps[NSEG];        // partial sum exp(x)
__device__ float g_pU[NSEG];        // partial sum x*exp(x)
__device__ float g_pc[NSEG];        // partial positive count
__device__ unsigned int g_done = 0; // arrival counter (reset by last block)

struct Acc { float s0, s1, U0, U1; int c; };

__device__ __forceinline__ void acc4(Acc& a, float4 v)
{
    float e0 = __expf(v.x), e1 = __expf(v.y);
    float e2 = __expf(v.z), e3 = __expf(v.w);
    bool p0 = v.x > 0.f, p1 = v.y > 0.f, p2 = v.z > 0.f, p3 = v.w > 0.f;
    e0 = p0 ? e0 : 0.f;  e1 = p1 ? e1 : 0.f;
    e2 = p2 ? e2 : 0.f;  e3 = p3 ? e3 : 0.f;
    a.s0 += e0;                  a.s1 += e1;
    a.U0 = fmaf(v.x, e0, a.U0);  a.U1 = fmaf(v.y, e1, a.U1);
    a.s0 += e2;                  a.s1 += e3;
    a.U0 = fmaf(v.z, e2, a.U0);  a.U1 = fmaf(v.w, e3, a.U1);
    a.c += (int)p0 + (int)p1 + (int)p2 + (int)p3;
}

__device__ __forceinline__ float4 zero4() { return make_float4(0.f, 0.f, 0.f, 0.f); }

__global__ void __launch_bounds__(TPB, 10)
entropy_fused(const float* __restrict__ in, float* __restrict__ out)
{
    for (int sidx = 0; sidx < SEG_PER_BLK; sidx++) {
        const int sg  = blockIdx.x + sidx * NBLK;   // 0..3039
        const int ch  = sg / SPLIT;                 // 0..159
        const int seg = sg % SPLIT;
        const int i0  = (int)(((long long)HW4 * seg) / SPLIT);
        const int i1  = (int)(((long long)HW4 * (seg + 1)) / SPLIT);
        const float4* __restrict__ p4 =
            reinterpret_cast<const float4*>(in + (size_t)ch * HW);

        Acc a = {0.f, 0.f, 0.f, 0.f, 0};

        int i = i0 + threadIdx.x;
        // prime the pipeline: 4 loads in flight
        float4 r0 = (i           < i1) ? __ldcs(p4 + i)           : zero4();
        float4 r1 = (i + TPB     < i1) ? __ldcs(p4 + i + TPB)     : zero4();
        float4 r2 = (i + 2 * TPB < i1) ? __ldcs(p4 + i + 2 * TPB) : zero4();
        float4 r3 = (i + 3 * TPB < i1) ? __ldcs(p4 + i + 3 * TPB) : zero4();

        #pragma unroll 1
        for (; i + 3 * TPB < i1; ) {
            const int j = i + 4 * TPB;   // prefetch indices
            float4 n0 = (j           < i1) ? __ldcs(p4 + j)           : zero4();
            float4 n1 = (j + TPB     < i1) ? __ldcs(p4 + j + TPB)     : zero4();
            float4 n2 = (j + 2 * TPB < i1) ? __ldcs(p4 + j + 2 * TPB) : zero4();
            float4 n3 = (j + 3 * TPB < i1) ? __ldcs(p4 + j + 3 * TPB) : zero4();
            acc4(a, r0); acc4(a, r1); acc4(a, r2); acc4(a, r3);
            r0 = n0; r1 = n1; r2 = n2; r3 = n3;
            i = j;
        }
        // drain: r0..r3 hold the last (possibly zero-padded) group
        acc4(a, r0); acc4(a, r1); acc4(a, r2); acc4(a, r3);

        float s   = a.s0 + a.s1;
        float U   = a.U0 + a.U1;
        float cnt = (float)a.c;

        // warp reduce
        #pragma unroll
        for (int o = 16; o > 0; o >>= 1) {
            s   += __shfl_down_sync(0xffffffffu, s,   o);
            U   += __shfl_down_sync(0xffffffffu, U,   o);
            cnt += __shfl_down_sync(0xffffffffu, cnt, o);
        }

        __shared__ float sh_s[TPB / 32], sh_U[TPB / 32], sh_c[TPB / 32];
        const int w = threadIdx.x >> 5;
        const int l = threadIdx.x & 31;
        if (l == 0) { sh_s[w] = s; sh_U[w] = U; sh_c[w] = cnt; }
        __syncthreads();

        if (threadIdx.x == 0) {
            float ts = 0.f, tU = 0.f, tc = 0.f;
            #pragma unroll
            for (int k = 0; k < TPB / 32; k++) { ts += sh_s[k]; tU += sh_U[k]; tc += sh_c[k]; }
            g_ps[sg] = ts; g_pU[sg] = tU; g_pc[sg] = tc;
        }
        __syncthreads();   // protect sh_* reuse across segments
    }

    // ---- arrival + last-block finalize ----
    __shared__ bool is_last;
    if (threadIdx.x == 0) {
        __threadfence();                       // publish partials before arrival
        unsigned int old = atomicAdd(&g_done, 1u);
        is_last = (old == NBLK - 1);
    }
    __syncthreads();
    if (!is_last) return;

    __threadfence();                           // acquire: see all partials

    __shared__ float ent_c[CHANNELS];
    __shared__ float cnt_c[CHANNELS];

    const int t = threadIdx.x;
    if (t == 0) g_done = 0;                    // reset for next graph replay
    for (int c = t; c < CHANNELS; c += TPB) {
        float ss = 0.f, UU = 0.f, cc = 0.f;
        #pragma unroll
        for (int k = 0; k < SPLIT; k++) {
            ss += g_ps[c * SPLIT + k];
            UU += g_pU[c * SPLIT + k];
            cc += g_pc[c * SPLIT + k];
        }
        float ent = 0.f;
        if (ss > 0.f) {
            const float INV_LN2 = 1.4426950408889634f;
            ent = (logf(ss) - UU / ss) * INV_LN2;
        }
        ent_c[c] = ent;
        cnt_c[c] = cc;
    }
    __syncthreads();

    if (t < N_BATCH) {
        float es = 0.f, cs = 0.f;
        #pragma unroll
        for (int c = 0; c < N_CH; c++) {
            es += ent_c[t * N_CH + c];
            cs += cnt_c[t * N_CH + c];
        }
        out[t] = es / cs;
    }
}

extern "C" void kernel_launch(void* const* d_in, const int* in_sizes, int n_in,
                              void* d_out, int out_size)
{
    const float* heatmap = (const float*)d_in[0];
    float* out = (float*)d_out;
    entropy_fused<<<NBLK, TPB>>>(heatmap, out);
}